// round 2
// baseline (speedup 1.0000x reference)
#include <cuda_runtime.h>
#include <cstdint>

// Global double accumulator (no device allocation allowed).
__device__ double g_energy_acc;

#define EPS 1e-06f

__global__ void zero_acc_kernel() {
    g_energy_acc = 0.0;
}

__global__ void __launch_bounds__(256)
spring_energy_kernel(const float* __restrict__ x,
                     const int2* __restrict__ indices,  // [E] pairs (int32,int32)
                     const float* __restrict__ l0,
                     const float* __restrict__ k,
                     long long E)
{
    long long e = (long long)blockIdx.x * blockDim.x + threadIdx.x;

    float term = 0.0f;
    if (e < E) {
        int2 ij = __ldg(indices + e);
        const float* xi = x + 3LL * ij.x;
        const float* xj = x + 3LL * ij.y;

        float d0 = __ldg(xi + 0) - __ldg(xj + 0);
        float d1 = __ldg(xi + 1) - __ldg(xj + 1);
        float d2 = __ldg(xi + 2) - __ldg(xj + 2);

        float q = fmaf(d0, d0, fmaf(d1, d1, d2 * d2));
        float l = sqrtf(q + EPS);
        float dl = l - __ldg(l0 + e);
        term = 0.5f * __ldg(k + e) * dl * dl;
    }

    // Warp reduction
    #pragma unroll
    for (int off = 16; off > 0; off >>= 1)
        term += __shfl_down_sync(0xFFFFFFFFu, term, off);

    // Block reduction via shared memory
    __shared__ float warp_sums[8];  // 256 threads / 32 warps
    int lane = threadIdx.x & 31;
    int wid  = threadIdx.x >> 5;
    if (lane == 0) warp_sums[wid] = term;
    __syncthreads();

    if (wid == 0) {
        float v = (lane < 8) ? warp_sums[lane] : 0.0f;
        #pragma unroll
        for (int off = 4; off > 0; off >>= 1)
            v += __shfl_down_sync(0xFFFFFFFFu, v, off);
        if (lane == 0)
            atomicAdd(&g_energy_acc, (double)v);
    }
}

__global__ void finalize_kernel(float* out) {
    out[0] = (float)g_energy_acc;
}

extern "C" void kernel_launch(void* const* d_in, const int* in_sizes, int n_in,
                              void* d_out, int out_size)
{
    // Input order per reference: x [V*3] f32, indices [E,2] int32, l0 [E] f32, k [E] f32
    const float* x       = (const float*)d_in[0];
    const int2*  indices = (const int2*)d_in[1];
    const float* l0      = (const float*)d_in[2];
    const float* k       = (const float*)d_in[3];
    float*       out     = (float*)d_out;

    long long E = (long long)in_sizes[2];  // l0 element count

    zero_acc_kernel<<<1, 1>>>();

    const int threads = 256;
    long long blocks = (E + threads - 1) / threads;
    spring_energy_kernel<<<(unsigned)blocks, threads>>>(x, indices, l0, k, E);

    finalize_kernel<<<1, 1>>>(out);
}

// round 3
// speedup vs baseline: 1.2025x; 1.2025x over previous
#include <cuda_runtime.h>
#include <cstdint>

#define EPS 1e-06f
#define MAX_V 2000000

// Scratch: padded vertex positions (16B-aligned rows) + global accumulator.
__device__ float4 g_x4[MAX_V];
__device__ double g_energy_acc;

// Repack x[V,3] -> g_x4[V] (w unused) and zero the accumulator.
__global__ void __launch_bounds__(256)
repack_kernel(const float* __restrict__ x, int V)
{
    int v = blockIdx.x * blockDim.x + threadIdx.x;
    if (v == 0) g_energy_acc = 0.0;
    if (v < V) {
        float a = __ldg(x + 3 * v + 0);
        float b = __ldg(x + 3 * v + 1);
        float c = __ldg(x + 3 * v + 2);
        g_x4[v] = make_float4(a, b, c, 0.0f);
    }
}

__global__ void __launch_bounds__(256)
spring_energy_kernel(const int2* __restrict__ indices,  // [E] (i,j) int32 pairs
                     const float* __restrict__ l0,
                     const float* __restrict__ k,
                     long long E)
{
    long long e = (long long)blockIdx.x * blockDim.x + threadIdx.x;

    float term = 0.0f;
    if (e < E) {
        int2 ij = __ldg(indices + e);
        float4 a = __ldg(&g_x4[ij.x]);   // one LDG.128 per endpoint
        float4 b = __ldg(&g_x4[ij.y]);

        float d0 = a.x - b.x;
        float d1 = a.y - b.y;
        float d2 = a.z - b.z;

        float q = fmaf(d0, d0, fmaf(d1, d1, d2 * d2));
        float l = sqrtf(q + EPS);
        float dl = l - __ldg(l0 + e);
        term = 0.5f * __ldg(k + e) * dl * dl;
    }

    // Warp reduction
    #pragma unroll
    for (int off = 16; off > 0; off >>= 1)
        term += __shfl_down_sync(0xFFFFFFFFu, term, off);

    // Block reduction
    __shared__ float warp_sums[8];
    int lane = threadIdx.x & 31;
    int wid  = threadIdx.x >> 5;
    if (lane == 0) warp_sums[wid] = term;
    __syncthreads();

    if (wid == 0) {
        float v = (lane < 8) ? warp_sums[lane] : 0.0f;
        #pragma unroll
        for (int off = 4; off > 0; off >>= 1)
            v += __shfl_down_sync(0xFFFFFFFFu, v, off);
        if (lane == 0)
            atomicAdd(&g_energy_acc, (double)v);
    }
}

// Fallback path (V > MAX_V): gather directly from x (unpadded rows).
__global__ void __launch_bounds__(256)
spring_energy_fallback_kernel(const float* __restrict__ x,
                              const int2* __restrict__ indices,
                              const float* __restrict__ l0,
                              const float* __restrict__ k,
                              long long E)
{
    long long e = (long long)blockIdx.x * blockDim.x + threadIdx.x;
    float term = 0.0f;
    if (e < E) {
        int2 ij = __ldg(indices + e);
        const float* xi = x + 3LL * ij.x;
        const float* xj = x + 3LL * ij.y;
        float d0 = __ldg(xi + 0) - __ldg(xj + 0);
        float d1 = __ldg(xi + 1) - __ldg(xj + 1);
        float d2 = __ldg(xi + 2) - __ldg(xj + 2);
        float q = fmaf(d0, d0, fmaf(d1, d1, d2 * d2));
        float l = sqrtf(q + EPS);
        float dl = l - __ldg(l0 + e);
        term = 0.5f * __ldg(k + e) * dl * dl;
    }
    #pragma unroll
    for (int off = 16; off > 0; off >>= 1)
        term += __shfl_down_sync(0xFFFFFFFFu, term, off);
    __shared__ float warp_sums[8];
    int lane = threadIdx.x & 31;
    int wid  = threadIdx.x >> 5;
    if (lane == 0) warp_sums[wid] = term;
    __syncthreads();
    if (wid == 0) {
        float v = (lane < 8) ? warp_sums[lane] : 0.0f;
        #pragma unroll
        for (int off = 4; off > 0; off >>= 1)
            v += __shfl_down_sync(0xFFFFFFFFu, v, off);
        if (lane == 0)
            atomicAdd(&g_energy_acc, (double)v);
    }
}

__global__ void zero_acc_kernel() { g_energy_acc = 0.0; }

__global__ void finalize_kernel(float* out) {
    out[0] = (float)g_energy_acc;
}

extern "C" void kernel_launch(void* const* d_in, const int* in_sizes, int n_in,
                              void* d_out, int out_size)
{
    // Inputs: x [V*3] f32, indices [E*2] i32, l0 [E] f32, k [E] f32
    const float* x       = (const float*)d_in[0];
    const int2*  indices = (const int2*)d_in[1];
    const float* l0      = (const float*)d_in[2];
    const float* k       = (const float*)d_in[3];
    float*       out     = (float*)d_out;

    int       V = in_sizes[0] / 3;
    long long E = (long long)in_sizes[2];

    const int threads = 256;
    long long eblocks = (E + threads - 1) / threads;

    if (V <= MAX_V) {
        int vblocks = (V + threads - 1) / threads;
        repack_kernel<<<vblocks, threads>>>(x, V);
        spring_energy_kernel<<<(unsigned)eblocks, threads>>>(indices, l0, k, E);
    } else {
        zero_acc_kernel<<<1, 1>>>();
        spring_energy_fallback_kernel<<<(unsigned)eblocks, threads>>>(x, indices, l0, k, E);
    }

    finalize_kernel<<<1, 1>>>(out);
}

// round 4
// speedup vs baseline: 1.3148x; 1.0933x over previous
#include <cuda_runtime.h>
#include <cstdint>

#define EPS 1e-06f
#define MAX_V 2000000

__device__ float4 g_x4[MAX_V];
__device__ double g_energy_acc;

// Repack x[V,3] -> g_x4[V] (w=0), 4 vertices per thread, vectorized.
__global__ void __launch_bounds__(256)
repack_kernel(const float* __restrict__ x, int V)
{
    int t = blockIdx.x * blockDim.x + threadIdx.x;
    if (t == 0 && blockIdx.x == 0) g_energy_acc = 0.0;
    int v0 = 4 * t;
    if (v0 + 3 < V) {
        const float4* xs = (const float4*)(x + 3 * v0);  // 48B = 3 x float4
        float4 a = __ldg(xs + 0);
        float4 b = __ldg(xs + 1);
        float4 c = __ldg(xs + 2);
        g_x4[v0 + 0] = make_float4(a.x, a.y, a.z, 0.0f);
        g_x4[v0 + 1] = make_float4(a.w, b.x, b.y, 0.0f);
        g_x4[v0 + 2] = make_float4(b.z, b.w, c.x, 0.0f);
        g_x4[v0 + 3] = make_float4(c.y, c.z, c.w, 0.0f);
    } else {
        for (int v = v0; v < V; v++) {
            g_x4[v] = make_float4(__ldg(x + 3 * v + 0),
                                  __ldg(x + 3 * v + 1),
                                  __ldg(x + 3 * v + 2), 0.0f);
        }
    }
}

__device__ __forceinline__ float edge_term(int i, int j, float l0v, float kv)
{
    float4 a = __ldg(&g_x4[i]);
    float4 b = __ldg(&g_x4[j]);
    float d0 = a.x - b.x;
    float d1 = a.y - b.y;
    float d2 = a.z - b.z;
    float q  = fmaf(d0, d0, fmaf(d1, d1, d2 * d2));
    float l  = sqrtf(q + EPS);
    float dl = l - l0v;
    return 0.5f * kv * dl * dl;
}

// 4 edges per thread: int4 x2 index loads, float4 l0/k loads, 8 gathers in flight.
__global__ void __launch_bounds__(256)
spring_energy_kernel(const int* __restrict__ indices,  // [E*2] int32
                     const float* __restrict__ l0,
                     const float* __restrict__ k,
                     long long E)
{
    long long t    = (long long)blockIdx.x * blockDim.x + threadIdx.x;
    long long base = 4 * t;

    float term = 0.0f;
    if (base + 3 < E) {
        // 2 x int4 = indices for 4 edges (32B per thread, coalesced)
        int4 p = __ldg((const int4*)(indices + 2 * base));
        int4 q = __ldg((const int4*)(indices + 2 * base) + 1);
        float4 l04 = __ldg((const float4*)(l0 + base));
        float4 k4  = __ldg((const float4*)(k  + base));

        // Batch all 8 gathers up front for max MLP.
        float4 a0 = __ldg(&g_x4[p.x]);
        float4 b0 = __ldg(&g_x4[p.y]);
        float4 a1 = __ldg(&g_x4[p.z]);
        float4 b1 = __ldg(&g_x4[p.w]);
        float4 a2 = __ldg(&g_x4[q.x]);
        float4 b2 = __ldg(&g_x4[q.y]);
        float4 a3 = __ldg(&g_x4[q.z]);
        float4 b3 = __ldg(&g_x4[q.w]);

        float d0, d1, d2, qq, l, dl;

        d0 = a0.x - b0.x; d1 = a0.y - b0.y; d2 = a0.z - b0.z;
        qq = fmaf(d0, d0, fmaf(d1, d1, d2 * d2));
        l  = sqrtf(qq + EPS); dl = l - l04.x;
        term = fmaf(0.5f * k4.x, dl * dl, term);

        d0 = a1.x - b1.x; d1 = a1.y - b1.y; d2 = a1.z - b1.z;
        qq = fmaf(d0, d0, fmaf(d1, d1, d2 * d2));
        l  = sqrtf(qq + EPS); dl = l - l04.y;
        term = fmaf(0.5f * k4.y, dl * dl, term);

        d0 = a2.x - b2.x; d1 = a2.y - b2.y; d2 = a2.z - b2.z;
        qq = fmaf(d0, d0, fmaf(d1, d1, d2 * d2));
        l  = sqrtf(qq + EPS); dl = l - l04.z;
        term = fmaf(0.5f * k4.z, dl * dl, term);

        d0 = a3.x - b3.x; d1 = a3.y - b3.y; d2 = a3.z - b3.z;
        qq = fmaf(d0, d0, fmaf(d1, d1, d2 * d2));
        l  = sqrtf(qq + EPS); dl = l - l04.w;
        term = fmaf(0.5f * k4.w, dl * dl, term);
    } else {
        for (long long e = base; e < E; e++) {
            int i = __ldg(indices + 2 * e);
            int j = __ldg(indices + 2 * e + 1);
            term += edge_term(i, j, __ldg(l0 + e), __ldg(k + e));
        }
    }

    // Warp reduction
    #pragma unroll
    for (int off = 16; off > 0; off >>= 1)
        term += __shfl_down_sync(0xFFFFFFFFu, term, off);

    // Block reduction
    __shared__ float warp_sums[8];
    int lane = threadIdx.x & 31;
    int wid  = threadIdx.x >> 5;
    if (lane == 0) warp_sums[wid] = term;
    __syncthreads();

    if (wid == 0) {
        float v = (lane < 8) ? warp_sums[lane] : 0.0f;
        #pragma unroll
        for (int off = 4; off > 0; off >>= 1)
            v += __shfl_down_sync(0xFFFFFFFFu, v, off);
        if (lane == 0)
            atomicAdd(&g_energy_acc, (double)v);
    }
}

// Fallback (V > MAX_V): direct scalar gather from x.
__global__ void __launch_bounds__(256)
spring_energy_fallback_kernel(const float* __restrict__ x,
                              const int2* __restrict__ indices,
                              const float* __restrict__ l0,
                              const float* __restrict__ k,
                              long long E)
{
    long long e = (long long)blockIdx.x * blockDim.x + threadIdx.x;
    float term = 0.0f;
    if (e < E) {
        int2 ij = __ldg(indices + e);
        const float* xi = x + 3LL * ij.x;
        const float* xj = x + 3LL * ij.y;
        float d0 = __ldg(xi + 0) - __ldg(xj + 0);
        float d1 = __ldg(xi + 1) - __ldg(xj + 1);
        float d2 = __ldg(xi + 2) - __ldg(xj + 2);
        float q = fmaf(d0, d0, fmaf(d1, d1, d2 * d2));
        float l = sqrtf(q + EPS);
        float dl = l - __ldg(l0 + e);
        term = 0.5f * __ldg(k + e) * dl * dl;
    }
    #pragma unroll
    for (int off = 16; off > 0; off >>= 1)
        term += __shfl_down_sync(0xFFFFFFFFu, term, off);
    __shared__ float warp_sums[8];
    int lane = threadIdx.x & 31;
    int wid  = threadIdx.x >> 5;
    if (lane == 0) warp_sums[wid] = term;
    __syncthreads();
    if (wid == 0) {
        float v = (lane < 8) ? warp_sums[lane] : 0.0f;
        #pragma unroll
        for (int off = 4; off > 0; off >>= 1)
            v += __shfl_down_sync(0xFFFFFFFFu, v, off);
        if (lane == 0)
            atomicAdd(&g_energy_acc, (double)v);
    }
}

__global__ void zero_acc_kernel() { g_energy_acc = 0.0; }

__global__ void finalize_kernel(float* out) {
    out[0] = (float)g_energy_acc;
}

extern "C" void kernel_launch(void* const* d_in, const int* in_sizes, int n_in,
                              void* d_out, int out_size)
{
    const float* x       = (const float*)d_in[0];
    const int*   indices = (const int*)d_in[1];
    const float* l0      = (const float*)d_in[2];
    const float* k       = (const float*)d_in[3];
    float*       out     = (float*)d_out;

    int       V = in_sizes[0] / 3;
    long long E = (long long)in_sizes[2];

    const int threads = 256;

    if (V <= MAX_V) {
        int vblocks = (V / 4 + threads - 1) / threads;
        repack_kernel<<<vblocks, threads>>>(x, V);
        long long eblocks = (E + 4LL * threads - 1) / (4LL * threads);
        spring_energy_kernel<<<(unsigned)eblocks, threads>>>(indices, l0, k, E);
    } else {
        zero_acc_kernel<<<1, 1>>>();
        long long eblocks = (E + threads - 1) / threads;
        spring_energy_fallback_kernel<<<(unsigned)eblocks, threads>>>(
            x, (const int2*)indices, l0, k, E);
    }

    finalize_kernel<<<1, 1>>>(out);
}